// round 16
// baseline (speedup 1.0000x reference)
#include <cuda_runtime.h>

#define NB     16     // batch
#define NT     256    // timesteps
#define NIN    6
#define NHID   256
#define NFEAT  64
#define NSTATE 64
#define NMOTOR 16
#define NUNF   6
#define EPSV   1e-8f

// scratch: state-independent sensory sums  [B,T,STATE]
__device__ float g_num[NB * NT * NSTATE];
__device__ float g_den[NB * NT * NSTATE];
// packed/transposed weight tables (built by setup_tables each launch)
__device__ float4 g_ctab[NFEAT * NSTATE];       // (0.5s, 0.5ms, 0.5we, 0.5w)
__device__ float  g_pw2t[NSTATE * NHID];        // pw2 transposed [j][h]
__device__ float  g_pw1t[NHID * 8];             // pw1 transposed [h][k], k6=bias

__device__ __forceinline__ float tanh_fast(float x) {
    float y;
    asm("tanh.approx.f32 %0, %1;" : "=f"(y) : "f"(x));
    return y;
}

__device__ __forceinline__ float fastdiv(float a, float b) {
    float r, q;
    asm("rcp.approx.f32 %0, %1;" : "=f"(r) : "f"(b));
    asm("mul.f32 %0, %1, %2;" : "=f"(q) : "f"(a), "f"(r));
    return q;
}

// ---------------------------------------------------------------------------
// Kernel 0: build packed tables. 64 blocks x 256 threads, ~2us.
// Deterministic pure function of inputs -> graph/replay safe.
// ---------------------------------------------------------------------------
__global__ __launch_bounds__(256)
void setup_tables(const float* __restrict__ pw1, const float* __restrict__ pb1,
                  const float* __restrict__ pw2,
                  const float* __restrict__ sw,  const float* __restrict__ smu,
                  const float* __restrict__ ssig, const float* __restrict__ serev)
{
    const int idx = blockIdx.x * 256 + threadIdx.x;   // 0..16383

    // pw2 transpose: pw2t[j*256+h] = pw2[h*64+j]
    {
        const int j = idx >> 8, h = idx & 255;
        g_pw2t[idx] = pw2[h * NFEAT + j];
    }
    // sensory synapse pack: one float4 per (f,j)
    if (idx < NFEAT * NSTATE) {
        float hsw = 0.5f * sw[idx];
        g_ctab[idx] = make_float4(0.5f * ssig[idx],
                                  0.5f * smu[idx] * ssig[idx],
                                  hsw * serev[idx],
                                  hsw);
    }
    // pw1 transpose+pad: pw1t[h*8+k], k<6 weights, k==6 bias, k==7 pad
    if (idx < NHID * 8) {
        const int h = idx >> 3, k = idx & 7;
        g_pw1t[idx] = (k < NIN) ? pw1[k * NHID + h]
                                : ((k == NIN) ? pb1[h] : 0.0f);
    }
}

// ---------------------------------------------------------------------------
// Kernel 1: prenet. 4096 independent blocks x 64 threads (max residency),
// ALL hot loads vectorized via the packed tables: ~280 warp-LDG per block
// vs ~1100 scalar before -> LSU floor drops 27us -> ~7us.
// ---------------------------------------------------------------------------
__global__ __launch_bounds__(64)
void prenet_sensory(const float* __restrict__ x,
                    const float* __restrict__ pb2,
                    const float* __restrict__ input_w, const float* __restrict__ input_b)
{
    __shared__ __align__(16) float hidden[NHID];
    __shared__ float featsh[NFEAT];

    const int bt  = blockIdx.x;           // (b,t) unit
    const int tid = threadIdx.x;          // 0..63 ; j = tid

    // phase A: 4 hidden units per thread via packed pw1t (2 LDG.128 each)
    {
        float xl[NIN];
        #pragma unroll
        for (int k = 0; k < NIN; k++) xl[k] = x[bt * NIN + k];
        #pragma unroll
        for (int c = 0; c < 4; c++) {
            const int h = tid * 4 + c;
            float4 wa = *reinterpret_cast<const float4*>(&g_pw1t[h * 8]);
            float4 wb = *reinterpret_cast<const float4*>(&g_pw1t[h * 8 + 4]);
            float s = wb.z;                       // bias
            s = fmaf(xl[0], wa.x, s);
            s = fmaf(xl[1], wa.y, s);
            s = fmaf(xl[2], wa.z, s);
            s = fmaf(xl[3], wa.w, s);
            s = fmaf(xl[4], wb.x, s);
            s = fmaf(xl[5], wb.y, s);
            hidden[h] = tanh_fast(s);
        }
    }
    __syncthreads();

    // phase B: feat[tid] = hidden . pw2t[tid,:] ; both sides in float4
    {
        float a0 = 0.f, a1 = 0.f, a2 = 0.f, a3 = 0.f;
        const float* wrow = &g_pw2t[tid * NHID];
        #pragma unroll 8
        for (int h = 0; h < NHID; h += 4) {
            float4 hv = *reinterpret_cast<const float4*>(&hidden[h]);
            float4 wv = *reinterpret_cast<const float4*>(&wrow[h]);
            a0 = fmaf(hv.x, wv.x, a0);
            a1 = fmaf(hv.y, wv.y, a1);
            a2 = fmaf(hv.z, wv.z, a2);
            a3 = fmaf(hv.w, wv.w, a3);
        }
        float f = (a0 + a1) + (a2 + a3) + pb2[tid];
        f = fmaf(f, input_w[tid], input_b[tid]);
        featsh[tid] = f;
    }
    __syncthreads();

    // phase C: 64 feats, ONE float4 load per synapse.
    //   th  = tanh(feat*0.5s - 0.5ms)
    //   np  = sum 0.5we*(th+1) = sum 0.5we*th + sum 0.5we   (split accums)
    {
        float npt = 0.f, npc = 0.f, dpt = 0.f, dpc = 0.f;
        #pragma unroll 8
        for (int f = 0; f < NFEAT; f++) {
            float4 c = g_ctab[f * NSTATE + tid];
            float th = tanh_fast(fmaf(featsh[f], c.x, -c.y));
            npt = fmaf(c.z, th, npt);
            npc += c.z;
            dpt = fmaf(c.w, th, dpt);
            dpc += c.w;
        }
        g_num[bt * NSTATE + tid] = npt + npc;
        g_den[bt * NSTATE + tid] = dpt + dpc;
    }
}

// ---------------------------------------------------------------------------
// Kernel 2: sequential LTC scan — proven R7 body (408us, rel_err 6.5e-6).
// One CTA per batch (16 CTAs), 128 threads (4 warps, one per SMSP).
// j = tid>>1, g = tid&1 (32 rows per thread). f32 tanh.approx only.
// One shfl level, double-buffered v, one barrier per unfold, LDG prefetch.
// ---------------------------------------------------------------------------
__global__ __launch_bounds__(128, 1)
void ltc_scan(const float* __restrict__ w_,    const float* __restrict__ mu_,
              const float* __restrict__ sigma_, const float* __restrict__ erev_,
              const float* __restrict__ gleak,  const float* __restrict__ vleak,
              const float* __restrict__ cm,
              const float* __restrict__ ow,     const float* __restrict__ ob,
              float* __restrict__ out)
{
    __shared__ __align__(16) float vsh[2][NSTATE];

    const int b   = blockIdx.x;
    const int tid = threadIdx.x;
    const int j   = tid >> 1;      // 0..63 post neuron
    const int g   = tid & 1;       // 0..1 row group (32 rows each)

    float hs[32], hb[32], hwe[32], hwv[32];
    float swe = 0.0f, swv = 0.0f;
    #pragma unroll
    for (int k = 0; k < 32; k++) {
        const int i   = g * 32 + k;
        const int idx = i * NSTATE + j;
        float wv  = w_[idx];
        float er  = erev_[idx];
        float sgv = sigma_[idx];
        float muv = mu_[idx];
        hwv[k] = 0.5f * wv;
        hwe[k] = 0.5f * wv * er;
        hs[k]  = 0.5f * sgv;
        hb[k]  = 0.5f * muv * sgv;
        swe += hwe[k];
        swv += hwv[k];
    }

    const float cm_t = cm[j] * (float)NUNF;
    const float gl   = gleak[j];
    const float leak = gl * vleak[j];
    const float denc = cm_t + gl + EPSV;
    float owv = 0.0f, obv = 0.0f;
    if (j < NMOTOR) { owv = ow[j]; obv = ob[j]; }

    if (tid < NSTATE) vsh[0][tid] = 0.0f;
    float vj = 0.0f;
    __syncthreads();

    const float* nb   = g_num + b * NT * NSTATE;
    const float* db   = g_den + b * NT * NSTATE;
    float*       outb = out   + b * NT * NMOTOR;

    float ns = nb[j];
    float ds = db[j];

    for (int t = 0; t < NT; t++) {
        const int tn = (t + 1 < NT) ? (t + 1) : t;
        float ns_next = nb[tn * NSTATE + j];
        float ds_next = db[tn * NSTATE + j];

        const float nsl = ns + leak;
        const float dsl = ds + denc;

        #pragma unroll
        for (int u = 0; u < NUNF; u++) {
            const int cur = u & 1;

            float np0 = swe, np1 = 0.f, np2 = 0.f, np3 = 0.f;
            float dp0 = swv, dp1 = 0.f, dp2 = 0.f, dp3 = 0.f;
            #pragma unroll
            for (int c = 0; c < 8; c++) {
                float4 vq = *reinterpret_cast<const float4*>(&vsh[cur][g * 32 + c * 4]);
                const int k = c * 4;
                float t0 = tanh_fast(fmaf(vq.x, hs[k + 0], -hb[k + 0]));
                float t1 = tanh_fast(fmaf(vq.y, hs[k + 1], -hb[k + 1]));
                float t2 = tanh_fast(fmaf(vq.z, hs[k + 2], -hb[k + 2]));
                float t3 = tanh_fast(fmaf(vq.w, hs[k + 3], -hb[k + 3]));
                np0 = fmaf(hwe[k + 0], t0, np0);
                np1 = fmaf(hwe[k + 1], t1, np1);
                np2 = fmaf(hwe[k + 2], t2, np2);
                np3 = fmaf(hwe[k + 3], t3, np3);
                dp0 = fmaf(hwv[k + 0], t0, dp0);
                dp1 = fmaf(hwv[k + 1], t1, dp1);
                dp2 = fmaf(hwv[k + 2], t2, dp2);
                dp3 = fmaf(hwv[k + 3], t3, dp3);
            }
            float dp = (dp0 + dp1) + (dp2 + dp3);
            float np = (np0 + np1) + (np2 + np3);

            dp += __shfl_xor_sync(0xffffffffu, dp, 1);
            np += __shfl_xor_sync(0xffffffffu, np, 1);

            float denom = dp + dsl;
            float numer = fmaf(cm_t, vj, np + nsl);
            vj = fastdiv(numer, denom);

            if (g == 0) vsh[cur ^ 1][j] = vj;
            __syncthreads();
        }

        if (j < NMOTOR && g == 0)
            outb[t * NMOTOR + j] = fmaf(vj, owv, obv);

        ns = ns_next;
        ds = ds_next;
    }
}

// ---------------------------------------------------------------------------
extern "C" void kernel_launch(void* const* d_in, const int* in_sizes, int n_in,
                              void* d_out, int out_size)
{
    const float* x        = (const float*)d_in[0];
    const float* pw1      = (const float*)d_in[1];
    const float* pb1      = (const float*)d_in[2];
    const float* pw2      = (const float*)d_in[3];
    const float* pb2      = (const float*)d_in[4];
    const float* input_w  = (const float*)d_in[5];
    const float* input_b  = (const float*)d_in[6];
    const float* sw       = (const float*)d_in[7];
    const float* smu      = (const float*)d_in[8];
    const float* ssig     = (const float*)d_in[9];
    const float* serev    = (const float*)d_in[10];
    const float* w_       = (const float*)d_in[11];
    const float* mu_      = (const float*)d_in[12];
    const float* sigma_   = (const float*)d_in[13];
    const float* erev_    = (const float*)d_in[14];
    const float* gleak    = (const float*)d_in[15];
    const float* vleak    = (const float*)d_in[16];
    const float* cm       = (const float*)d_in[17];
    const float* ow       = (const float*)d_in[18];
    const float* ob       = (const float*)d_in[19];
    float* out = (float*)d_out;

    setup_tables<<<64, 256>>>(pw1, pb1, pw2, sw, smu, ssig, serev);
    prenet_sensory<<<NB * NT, 64>>>(x, pb2, input_w, input_b);
    ltc_scan<<<NB, 128>>>(w_, mu_, sigma_, erev_, gleak, vleak, cm, ow, ob, out);
}

// round 17
// speedup vs baseline: 1.1517x; 1.1517x over previous
#include <cuda_runtime.h>

#define NB     16     // batch
#define NT     256    // timesteps
#define NIN    6
#define NHID   256
#define NFEAT  64
#define NSTATE 64
#define NMOTOR 16
#define NUNF   6
#define EPSV   1e-8f

// scratch: state-independent sensory sums  [B,T,STATE]
__device__ float g_num[NB * NT * NSTATE];
__device__ float g_den[NB * NT * NSTATE];
// packed sensory table (0.5s, 0.5ms, 0.5we, 0.5w) per (f,j) — coalesced in j
__device__ float4 g_ctab[NFEAT * NSTATE];

__device__ __forceinline__ float tanh_fast(float x) {
    float y;
    asm("tanh.approx.f32 %0, %1;" : "=f"(y) : "f"(x));
    return y;
}

__device__ __forceinline__ float fastdiv(float a, float b) {
    float r, q;
    asm("rcp.approx.f32 %0, %1;" : "=f"(r) : "f"(b));
    asm("mul.f32 %0, %1, %2;" : "=f"(q) : "f"(a), "f"(r));
    return q;
}

// ---------------------------------------------------------------------------
// Kernel 0: pack the sensory table only (coalesced load AND store). ~2us.
// ---------------------------------------------------------------------------
__global__ __launch_bounds__(256)
void setup_tables(const float* __restrict__ sw,  const float* __restrict__ smu,
                  const float* __restrict__ ssig, const float* __restrict__ serev)
{
    const int idx = blockIdx.x * 256 + threadIdx.x;   // 0..4095
    float hsw = 0.5f * sw[idx];
    g_ctab[idx] = make_float4(0.5f * ssig[idx],
                              0.5f * smu[idx] * ssig[idx],
                              hsw * serev[idx],
                              hsw);
}

// ---------------------------------------------------------------------------
// Kernel 1: prenet. 4096 independent blocks x 64 threads (max residency).
// All hot loads are LDG.128 along the THREAD axis (j / h-quad), i.e. original
// layouts, fully coalesced: ~280 warp-LDG and ~530 wavefronts per block
// (vs 1100/530 scalar in R5, vs 280/4600 in the failed R16 transpose).
// ---------------------------------------------------------------------------
__global__ __launch_bounds__(64)
void prenet_sensory(const float* __restrict__ x,
                    const float* __restrict__ pw1, const float* __restrict__ pb1,
                    const float* __restrict__ pw2, const float* __restrict__ pb2,
                    const float* __restrict__ input_w, const float* __restrict__ input_b)
{
    __shared__ __align__(16) float hidden[NHID];
    __shared__ __align__(16) float4 bpart[4][16];
    __shared__ __align__(16) float featsh[NFEAT];

    const int bt  = blockIdx.x;           // (b,t) unit
    const int tid = threadIdx.x;          // 0..63

    // phase A: hidden quad h = 4*tid..4*tid+3 ; 7 coalesced LDG.128
    {
        float xl[NIN];
        #pragma unroll
        for (int k = 0; k < NIN; k++) xl[k] = x[bt * NIN + k];

        const float4* pw1q = reinterpret_cast<const float4*>(pw1);
        float4 s = reinterpret_cast<const float4*>(pb1)[tid];
        #pragma unroll
        for (int k = 0; k < NIN; k++) {
            float4 w = pw1q[k * (NHID / 4) + tid];
            s.x = fmaf(xl[k], w.x, s.x);
            s.y = fmaf(xl[k], w.y, s.y);
            s.z = fmaf(xl[k], w.z, s.z);
            s.w = fmaf(xl[k], w.w, s.w);
        }
        float4 hq;
        hq.x = tanh_fast(s.x);
        hq.y = tanh_fast(s.y);
        hq.z = tanh_fast(s.z);
        hq.w = tanh_fast(s.w);
        *reinterpret_cast<float4*>(&hidden[tid * 4]) = hq;
    }
    __syncthreads();

    // phase B: thread (hq, jq) accumulates feats 4jq..4jq+3 over 64 h's.
    // pw2 float4 along j (original contiguous axis) -> coalesced LDG.128.
    {
        const int jq = tid & 15;          // feat quad
        const int hq = tid >> 4;          // h chunk
        const float4* pw2q = reinterpret_cast<const float4*>(pw2);
        float4 acc = make_float4(0.f, 0.f, 0.f, 0.f);
        const int h0 = hq * 64;
        #pragma unroll 8
        for (int h = 0; h < 64; h++) {
            float hv = hidden[h0 + h];
            float4 w = pw2q[(h0 + h) * (NFEAT / 4) + jq];
            acc.x = fmaf(hv, w.x, acc.x);
            acc.y = fmaf(hv, w.y, acc.y);
            acc.z = fmaf(hv, w.z, acc.z);
            acc.w = fmaf(hv, w.w, acc.w);
        }
        bpart[hq][jq] = acc;
    }
    __syncthreads();
    if (tid < 16) {
        float4 a = bpart[0][tid], b = bpart[1][tid];
        float4 c = bpart[2][tid], d = bpart[3][tid];
        float4 bias = reinterpret_cast<const float4*>(pb2)[tid];
        float4 iw   = reinterpret_cast<const float4*>(input_w)[tid];
        float4 ib   = reinterpret_cast<const float4*>(input_b)[tid];
        float4 f;
        f.x = fmaf((a.x + b.x) + (c.x + d.x) + bias.x, iw.x, ib.x);
        f.y = fmaf((a.y + b.y) + (c.y + d.y) + bias.y, iw.y, ib.y);
        f.z = fmaf((a.z + b.z) + (c.z + d.z) + bias.z, iw.z, ib.z);
        f.w = fmaf((a.w + b.w) + (c.w + d.w) + bias.w, iw.w, ib.w);
        *reinterpret_cast<float4*>(&featsh[tid * 4]) = f;
    }
    __syncthreads();

    // phase C: 64 feats, ONE coalesced float4 per synapse (j = tid).
    //   th = tanh(feat*0.5s - 0.5ms); np = sum 0.5we*th + sum 0.5we ; etc.
    {
        float npt = 0.f, npc = 0.f, dpt = 0.f, dpc = 0.f;
        #pragma unroll 8
        for (int f = 0; f < NFEAT; f++) {
            float4 c = g_ctab[f * NSTATE + tid];
            float th = tanh_fast(fmaf(featsh[f], c.x, -c.y));
            npt = fmaf(c.z, th, npt);
            npc += c.z;
            dpt = fmaf(c.w, th, dpt);
            dpc += c.w;
        }
        g_num[bt * NSTATE + tid] = npt + npc;
        g_den[bt * NSTATE + tid] = dpt + dpc;
    }
}

// ---------------------------------------------------------------------------
// Kernel 2: sequential LTC scan — proven R7 body (408us, rel_err 6.5e-6).
// One CTA per batch (16 CTAs), 128 threads (4 warps, one per SMSP).
// ---------------------------------------------------------------------------
__global__ __launch_bounds__(128, 1)
void ltc_scan(const float* __restrict__ w_,    const float* __restrict__ mu_,
              const float* __restrict__ sigma_, const float* __restrict__ erev_,
              const float* __restrict__ gleak,  const float* __restrict__ vleak,
              const float* __restrict__ cm,
              const float* __restrict__ ow,     const float* __restrict__ ob,
              float* __restrict__ out)
{
    __shared__ __align__(16) float vsh[2][NSTATE];

    const int b   = blockIdx.x;
    const int tid = threadIdx.x;
    const int j   = tid >> 1;      // 0..63 post neuron
    const int g   = tid & 1;       // 0..1 row group (32 rows each)

    float hs[32], hb[32], hwe[32], hwv[32];
    float swe = 0.0f, swv = 0.0f;
    #pragma unroll
    for (int k = 0; k < 32; k++) {
        const int i   = g * 32 + k;
        const int idx = i * NSTATE + j;
        float wv  = w_[idx];
        float er  = erev_[idx];
        float sgv = sigma_[idx];
        float muv = mu_[idx];
        hwv[k] = 0.5f * wv;
        hwe[k] = 0.5f * wv * er;
        hs[k]  = 0.5f * sgv;
        hb[k]  = 0.5f * muv * sgv;
        swe += hwe[k];
        swv += hwv[k];
    }

    const float cm_t = cm[j] * (float)NUNF;
    const float gl   = gleak[j];
    const float leak = gl * vleak[j];
    const float denc = cm_t + gl + EPSV;
    float owv = 0.0f, obv = 0.0f;
    if (j < NMOTOR) { owv = ow[j]; obv = ob[j]; }

    if (tid < NSTATE) vsh[0][tid] = 0.0f;
    float vj = 0.0f;
    __syncthreads();

    const float* nb   = g_num + b * NT * NSTATE;
    const float* db   = g_den + b * NT * NSTATE;
    float*       outb = out   + b * NT * NMOTOR;

    float ns = nb[j];
    float ds = db[j];

    for (int t = 0; t < NT; t++) {
        const int tn = (t + 1 < NT) ? (t + 1) : t;
        float ns_next = nb[tn * NSTATE + j];
        float ds_next = db[tn * NSTATE + j];

        const float nsl = ns + leak;
        const float dsl = ds + denc;

        #pragma unroll
        for (int u = 0; u < NUNF; u++) {
            const int cur = u & 1;

            float np0 = swe, np1 = 0.f, np2 = 0.f, np3 = 0.f;
            float dp0 = swv, dp1 = 0.f, dp2 = 0.f, dp3 = 0.f;
            #pragma unroll
            for (int c = 0; c < 8; c++) {
                float4 vq = *reinterpret_cast<const float4*>(&vsh[cur][g * 32 + c * 4]);
                const int k = c * 4;
                float t0 = tanh_fast(fmaf(vq.x, hs[k + 0], -hb[k + 0]));
                float t1 = tanh_fast(fmaf(vq.y, hs[k + 1], -hb[k + 1]));
                float t2 = tanh_fast(fmaf(vq.z, hs[k + 2], -hb[k + 2]));
                float t3 = tanh_fast(fmaf(vq.w, hs[k + 3], -hb[k + 3]));
                np0 = fmaf(hwe[k + 0], t0, np0);
                np1 = fmaf(hwe[k + 1], t1, np1);
                np2 = fmaf(hwe[k + 2], t2, np2);
                np3 = fmaf(hwe[k + 3], t3, np3);
                dp0 = fmaf(hwv[k + 0], t0, dp0);
                dp1 = fmaf(hwv[k + 1], t1, dp1);
                dp2 = fmaf(hwv[k + 2], t2, dp2);
                dp3 = fmaf(hwv[k + 3], t3, dp3);
            }
            float dp = (dp0 + dp1) + (dp2 + dp3);
            float np = (np0 + np1) + (np2 + np3);

            dp += __shfl_xor_sync(0xffffffffu, dp, 1);
            np += __shfl_xor_sync(0xffffffffu, np, 1);

            float denom = dp + dsl;
            float numer = fmaf(cm_t, vj, np + nsl);
            vj = fastdiv(numer, denom);

            if (g == 0) vsh[cur ^ 1][j] = vj;
            __syncthreads();
        }

        if (j < NMOTOR && g == 0)
            outb[t * NMOTOR + j] = fmaf(vj, owv, obv);

        ns = ns_next;
        ds = ds_next;
    }
}

// ---------------------------------------------------------------------------
extern "C" void kernel_launch(void* const* d_in, const int* in_sizes, int n_in,
                              void* d_out, int out_size)
{
    const float* x        = (const float*)d_in[0];
    const float* pw1      = (const float*)d_in[1];
    const float* pb1      = (const float*)d_in[2];
    const float* pw2      = (const float*)d_in[3];
    const float* pb2      = (const float*)d_in[4];
    const float* input_w  = (const float*)d_in[5];
    const float* input_b  = (const float*)d_in[6];
    const float* sw       = (const float*)d_in[7];
    const float* smu      = (const float*)d_in[8];
    const float* ssig     = (const float*)d_in[9];
    const float* serev    = (const float*)d_in[10];
    const float* w_       = (const float*)d_in[11];
    const float* mu_      = (const float*)d_in[12];
    const float* sigma_   = (const float*)d_in[13];
    const float* erev_    = (const float*)d_in[14];
    const float* gleak    = (const float*)d_in[15];
    const float* vleak    = (const float*)d_in[16];
    const float* cm       = (const float*)d_in[17];
    const float* ow       = (const float*)d_in[18];
    const float* ob       = (const float*)d_in[19];
    float* out = (float*)d_out;

    setup_tables<<<16, 256>>>(sw, smu, ssig, serev);
    prenet_sensory<<<NB * NT, 64>>>(x, pw1, pb1, pw2, pb2, input_w, input_b);
    ltc_scan<<<NB, 128>>>(w_, mu_, sigma_, erev_, gleak, vleak, cm, ow, ob, out);
}